// round 13
// baseline (speedup 1.0000x reference)
#include <cuda_runtime.h>
#include <cuda_fp16.h>

#define NN 50000
#define EE 1600000
#define CC 48
#define SS 10

// Scratch (allocation-free: __device__ globals)
__device__ float  g_deg[NN];
__device__ int    g_cnt[NN];
__device__ int    g_off[NN + 4];       // padded for int4 stores
__device__ int    g_pos[NN];
__device__ float2 g_csc[EE];           // {src_as_float, p}
__device__ float  g_h1f[NN * CC];      // fp32 step-1 accumulator (scattered in build)
__device__ __half g_h[SS][NN * CC];    // all 10 step states, fp16 (4.8 MB each)

// ---------- pass 1: src-degree (for norm) + dst-count (for CSC), 2 edges/thread ----------
__global__ void count_deg_kernel(const int* __restrict__ ei,
                                 const float* __restrict__ ea) {
    int t = blockIdx.x * blockDim.x + threadIdx.x;
    int e = t * 2;
    if (e < EE) {
        int2   r2 = *reinterpret_cast<const int2*>(ei + e);
        int2   c2 = *reinterpret_cast<const int2*>(ei + EE + e);
        float2 a2 = *reinterpret_cast<const float2*>(ea + e);
        atomicAdd(&g_deg[r2.x], a2.x);
        atomicAdd(&g_deg[r2.y], a2.y);
        atomicAdd(&g_cnt[c2.x], 1);
        atomicAdd(&g_cnt[c2.y], 1);
    }
}

// ---------- pass 2: single-block exclusive scan, 4 elems/thread ----------
__global__ void scan_kernel() {
    __shared__ int warp_sums[32];
    __shared__ int s_carry;
    int tid = threadIdx.x;
    int lane = tid & 31, wid = tid >> 5;
    if (tid == 0) s_carry = 0;
    __syncthreads();

    for (int base = 0; base < NN; base += 4096) {
        int idx = base + tid * 4;
        int4 v = make_int4(0, 0, 0, 0);
        if (idx < NN) v = reinterpret_cast<const int4*>(g_cnt)[idx >> 2];
        int s0 = v.x;
        int s01 = s0 + v.y;
        int s012 = s01 + v.z;
        int tot = s012 + v.w;
        int x = tot;
        #pragma unroll
        for (int o = 1; o < 32; o <<= 1) {
            int y = __shfl_up_sync(0xFFFFFFFF, x, o);
            if (lane >= o) x += y;
        }
        if (lane == 31) warp_sums[wid] = x;
        __syncthreads();
        if (wid == 0) {
            int w = warp_sums[lane];
            #pragma unroll
            for (int o = 1; o < 32; o <<= 1) {
                int y = __shfl_up_sync(0xFFFFFFFF, w, o);
                if (lane >= o) w += y;
            }
            warp_sums[lane] = w;
        }
        __syncthreads();
        int excl = x - tot + (wid > 0 ? warp_sums[wid - 1] : 0);
        int e0 = s_carry + excl;
        if (idx < NN) {
            int4 outs = make_int4(e0, e0 + s0, e0 + s01, e0 + s012);
            reinterpret_cast<int4*>(g_off)[idx >> 2] = outs;
            reinterpret_cast<int4*>(g_pos)[idx >> 2] = outs;
        }
        __syncthreads();
        if (tid == 1023) s_carry += warp_sums[31];
        __syncthreads();
    }
    if (tid == 0) g_off[NN] = s_carry;
}

// ---------- pass 3: build CSC (norm folded in) + step-1 one-hot scatter ----------
__global__ void build_csc_kernel(const int* __restrict__ ei,
                                 const float* __restrict__ ea,
                                 const int* __restrict__ target) {
    int e = blockIdx.x * blockDim.x + threadIdx.x;
    if (e < EE) {
        int r = ei[e];
        int c = ei[EE + e];
        float p = ea[e] / fmaxf(g_deg[r], 1e-12f);
        int pos = atomicAdd(&g_pos[c], 1);
        g_csc[pos] = make_float2(__int_as_float(r), p);
        // step 1 landing mass: h1[c][target[r]] += p  (h0 is one-hot(target))
        int tc = __ldg(&target[r]);
        atomicAdd(&g_h1f[c * CC + tc], p);
    }
}

__device__ __forceinline__ uint2 pack_half4(float4 a) {
    uint2 o;
    __half2 lo = __float22half2_rn(make_float2(a.x, a.y));
    __half2 hi = __float22half2_rn(make_float2(a.z, a.w));
    o.x = *reinterpret_cast<unsigned*>(&lo);
    o.y = *reinterpret_cast<unsigned*>(&hi);
    return o;
}

// ---------- finalize step 1: h1f(fp32) -> g_h[0](fp16) ----------
__global__ void finalize0_kernel(__half* __restrict__ hdst) {
    int i = blockIdx.x * blockDim.x + threadIdx.x;   // float4 index over NN*CC
    if (i >= NN * CC / 4) return;
    float4 v = reinterpret_cast<const float4*>(g_h1f)[i];
    reinterpret_cast<uint2*>(hdst)[i] = pack_half4(v);
}

// ---------- steps 2..10: fp16 CSC gather SpMM ----------
// 6 threads per node, thread c6 owns 8 halves at [c6*8, c6*8+8); 16B loads
__global__ void gather_kernel(const __half* __restrict__ hsrc,
                              __half* __restrict__ hdst) {
    int node = blockIdx.x * 32 + threadIdx.x / 6;
    int c6 = threadIdx.x % 6;
    if (node >= NN) return;
    int beg = g_off[node], end = g_off[node + 1];
    float acc0 = 0.f, acc1 = 0.f, acc2 = 0.f, acc3 = 0.f;
    float acc4 = 0.f, acc5 = 0.f, acc6 = 0.f, acc7 = 0.f;

    int j = beg;
    int n2 = beg + (((end - beg) >> 1) << 1);
    for (; j < n2; j += 2) {
        float2 e0 = __ldg(&g_csc[j]);
        float2 e1 = __ldg(&g_csc[j + 1]);
        uint4 r0 = __ldg(reinterpret_cast<const uint4*>(hsrc + __float_as_int(e0.x) * CC) + c6);
        uint4 r1 = __ldg(reinterpret_cast<const uint4*>(hsrc + __float_as_int(e1.x) * CC) + c6);
        float2 a0 = __half22float2(*reinterpret_cast<__half2*>(&r0.x));
        float2 a1 = __half22float2(*reinterpret_cast<__half2*>(&r0.y));
        float2 a2 = __half22float2(*reinterpret_cast<__half2*>(&r0.z));
        float2 a3 = __half22float2(*reinterpret_cast<__half2*>(&r0.w));
        acc0 = fmaf(e0.y, a0.x, acc0);
        acc1 = fmaf(e0.y, a0.y, acc1);
        acc2 = fmaf(e0.y, a1.x, acc2);
        acc3 = fmaf(e0.y, a1.y, acc3);
        acc4 = fmaf(e0.y, a2.x, acc4);
        acc5 = fmaf(e0.y, a2.y, acc5);
        acc6 = fmaf(e0.y, a3.x, acc6);
        acc7 = fmaf(e0.y, a3.y, acc7);
        float2 b0 = __half22float2(*reinterpret_cast<__half2*>(&r1.x));
        float2 b1 = __half22float2(*reinterpret_cast<__half2*>(&r1.y));
        float2 b2 = __half22float2(*reinterpret_cast<__half2*>(&r1.z));
        float2 b3 = __half22float2(*reinterpret_cast<__half2*>(&r1.w));
        acc0 = fmaf(e1.y, b0.x, acc0);
        acc1 = fmaf(e1.y, b0.y, acc1);
        acc2 = fmaf(e1.y, b1.x, acc2);
        acc3 = fmaf(e1.y, b1.y, acc3);
        acc4 = fmaf(e1.y, b2.x, acc4);
        acc5 = fmaf(e1.y, b2.y, acc5);
        acc6 = fmaf(e1.y, b3.x, acc6);
        acc7 = fmaf(e1.y, b3.y, acc7);
    }
    if (j < end) {
        float2 ed = __ldg(&g_csc[j]);
        uint4 r0 = __ldg(reinterpret_cast<const uint4*>(hsrc + __float_as_int(ed.x) * CC) + c6);
        float2 a0 = __half22float2(*reinterpret_cast<__half2*>(&r0.x));
        float2 a1 = __half22float2(*reinterpret_cast<__half2*>(&r0.y));
        float2 a2 = __half22float2(*reinterpret_cast<__half2*>(&r0.z));
        float2 a3 = __half22float2(*reinterpret_cast<__half2*>(&r0.w));
        acc0 = fmaf(ed.y, a0.x, acc0);
        acc1 = fmaf(ed.y, a0.y, acc1);
        acc2 = fmaf(ed.y, a1.x, acc2);
        acc3 = fmaf(ed.y, a1.y, acc3);
        acc4 = fmaf(ed.y, a2.x, acc4);
        acc5 = fmaf(ed.y, a2.y, acc5);
        acc6 = fmaf(ed.y, a3.x, acc6);
        acc7 = fmaf(ed.y, a3.y, acc7);
    }

    uint4 outp;
    __half2 p0 = __float22half2_rn(make_float2(acc0, acc1));
    __half2 p1 = __float22half2_rn(make_float2(acc2, acc3));
    __half2 p2 = __float22half2_rn(make_float2(acc4, acc5));
    __half2 p3 = __float22half2_rn(make_float2(acc6, acc7));
    outp.x = *reinterpret_cast<unsigned*>(&p0);
    outp.y = *reinterpret_cast<unsigned*>(&p1);
    outp.z = *reinterpret_cast<unsigned*>(&p2);
    outp.w = *reinterpret_cast<unsigned*>(&p3);
    reinterpret_cast<uint4*>(hdst + node * CC)[c6] = outp;
}

// ---------- final combine: out[n][c] = sum_s h_s[n][c] * w[c][s] ----------
__global__ void combine_kernel(float* __restrict__ out,
                               const float* __restrict__ weight) {
    int i = blockIdx.x * blockDim.x + threadIdx.x;   // float4 index over NN*CC
    if (i >= NN * CC / 4) return;
    int c4 = i % 12;
    int cbase = c4 * 4;
    float4 o = make_float4(0.f, 0.f, 0.f, 0.f);
    #pragma unroll
    for (int s = 0; s < SS; s++) {
        uint2 raw = __ldg(reinterpret_cast<const uint2*>(g_h[s]) + i);
        float2 fa = __half22float2(*reinterpret_cast<__half2*>(&raw.x));
        float2 fb = __half22float2(*reinterpret_cast<__half2*>(&raw.y));
        float w0 = __ldg(&weight[(cbase + 0) * SS + s]);
        float w1 = __ldg(&weight[(cbase + 1) * SS + s]);
        float w2 = __ldg(&weight[(cbase + 2) * SS + s]);
        float w3 = __ldg(&weight[(cbase + 3) * SS + s]);
        o.x = fmaf(w0, fa.x, o.x);
        o.y = fmaf(w1, fa.y, o.y);
        o.z = fmaf(w2, fb.x, o.z);
        o.w = fmaf(w3, fb.y, o.w);
    }
    reinterpret_cast<float4*>(out)[i] = o;
}

extern "C" void kernel_launch(void* const* d_in, const int* in_sizes, int n_in,
                              void* d_out, int out_size) {
    const int*   ei     = (const int*)d_in[0];    // [2, E]
    const float* ea     = (const float*)d_in[1];  // [E]
    const int*   target = (const int*)d_in[2];    // [N]
    const float* weight = (const float*)d_in[3];  // [C, S]
    float* out = (float*)d_out;                   // [N, C]

    void* p_deg;  cudaGetSymbolAddress(&p_deg,  g_deg);
    void* p_cnt;  cudaGetSymbolAddress(&p_cnt,  g_cnt);
    void* p_h1f;  cudaGetSymbolAddress(&p_h1f,  g_h1f);
    void* p_h;    cudaGetSymbolAddress(&p_h,    g_h);

    cudaMemsetAsync(p_deg, 0, NN * sizeof(float), 0);
    cudaMemsetAsync(p_cnt, 0, NN * sizeof(int), 0);
    cudaMemsetAsync(p_h1f, 0, (size_t)NN * CC * sizeof(float), 0);

    count_deg_kernel<<<(EE / 2 + 255) / 256, 256>>>(ei, ea);
    scan_kernel<<<1, 1024>>>();
    build_csc_kernel<<<(EE + 255) / 256, 256>>>(ei, ea, target);

    __half* h = (__half*)p_h;
    const size_t HSTRIDE = (size_t)NN * CC;

    // finalize step 1: convert scattered h1 to fp16 -> g_h[0]
    finalize0_kernel<<<(NN * CC / 4 + 255) / 256, 256>>>(h);

    const int node_blocks = (NN + 31) / 32;
    for (int s = 1; s < SS; s++) {
        gather_kernel<<<node_blocks, 192>>>(h + (s - 1) * HSTRIDE, h + s * HSTRIDE);
    }

    combine_kernel<<<(NN * CC / 4 + 255) / 256, 256>>>(out, weight);
}